// round 3
// baseline (speedup 1.0000x reference)
#include <cuda_runtime.h>

// CrossModalAttention: B=4, N=2048, DIM=512, H=8, Dh=64, fp32.
// Pipeline: [qkv_gemm] -> [attn_kernel (flash, constant-fill mask)] -> [out_gemm]

#define HEADS 8
#define DH 64
#define DIMC 512
#define BATCH 4
#define SEQ 2048
#define TOK (BATCH * SEQ)           // 8192
#define ATT_SCALE 0.125f            // 64^-0.5

// Scratch (allocation-free rule: __device__ globals). 4 x 16 MB.
__device__ float g_q[TOK * DIMC];
__device__ float g_k[TOK * DIMC];
__device__ float g_v[TOK * DIMC];
__device__ float g_att[TOK * DIMC];

// ---------------------------------------------------------------------------
// GEMM: C[m][n] = sum_k A[m*K+k] * B[n*K+k]   (A row-major [M,512], B row-major
// [512,512], both K-contiguous -> A * B^T). 64x64 block tile, BK=16, 256 thr,
// 4x4 micro-tile per thread. Per k-step: 2 LDS.128 : 16 FFMA.
// Global loads are register-prefetched one k-tile ahead so LDG latency
// overlaps the 16-step FFMA block instead of sitting between barriers.
// ---------------------------------------------------------------------------
__device__ __forceinline__ void gemm_body(const float* __restrict__ A,
                                          const float* __restrict__ B,
                                          float* __restrict__ C) {
  __shared__ float As[16][68];
  __shared__ float Bs[16][68];
  const int t = threadIdx.x;
  const int tx = t & 15, ty = t >> 4;
  const int row0 = blockIdx.y << 6;
  const int col0 = blockIdx.x << 6;
  const int lr = t >> 2;            // 0..63 tile row
  const int lk = (t & 3) << 2;      // 0,4,8,12 k-offset
  const float* Ag = A + (row0 + lr) * DIMC + lk;
  const float* Bg = B + (col0 + lr) * DIMC + lk;

  float acc[4][4];
#pragma unroll
  for (int i = 0; i < 4; i++)
#pragma unroll
    for (int j = 0; j < 4; j++) acc[i][j] = 0.f;

  float4 av = *(const float4*)(Ag);
  float4 bv = *(const float4*)(Bg);

  for (int k0 = 0; k0 < DIMC; k0 += 16) {
    As[lk + 0][lr] = av.x; As[lk + 1][lr] = av.y;
    As[lk + 2][lr] = av.z; As[lk + 3][lr] = av.w;
    Bs[lk + 0][lr] = bv.x; Bs[lk + 1][lr] = bv.y;
    Bs[lk + 2][lr] = bv.z; Bs[lk + 3][lr] = bv.w;
    __syncthreads();
    if (k0 + 16 < DIMC) {          // prefetch next k-tile during compute
      av = *(const float4*)(Ag + k0 + 16);
      bv = *(const float4*)(Bg + k0 + 16);
    }
#pragma unroll
    for (int k = 0; k < 16; k++) {
      float4 a4 = *(const float4*)&As[k][ty << 2];
      float4 b4 = *(const float4*)&Bs[k][tx << 2];
      float ar[4] = {a4.x, a4.y, a4.z, a4.w};
      float br[4] = {b4.x, b4.y, b4.z, b4.w};
#pragma unroll
      for (int i = 0; i < 4; i++)
#pragma unroll
        for (int j = 0; j < 4; j++) acc[i][j] = fmaf(ar[i], br[j], acc[i][j]);
    }
    __syncthreads();
  }
#pragma unroll
  for (int i = 0; i < 4; i++) {
    float4 v = make_float4(acc[i][0], acc[i][1], acc[i][2], acc[i][3]);
    *(float4*)&C[(row0 + (ty << 2) + i) * DIMC + col0 + (tx << 2)] = v;
  }
}

__global__ __launch_bounds__(256) void qkv_gemm(const float* __restrict__ x,
                                                const float* __restrict__ Wq,
                                                const float* __restrict__ Wk,
                                                const float* __restrict__ Wv) {
  const float* W = (blockIdx.z == 0) ? Wq : (blockIdx.z == 1) ? Wk : Wv;
  float* C = (blockIdx.z == 0) ? g_q : (blockIdx.z == 1) ? g_k : g_v;
  gemm_body(x, W, C);
}

__global__ __launch_bounds__(256) void out_gemm(const float* __restrict__ Wout,
                                                float* __restrict__ out) {
  gemm_body(g_att, Wout, out);
}

// ---------------------------------------------------------------------------
// Flash attention, fp32, one block per (q-tile of 64 rows, head, batch).
// Reference-faithful masking: masked score = constant 1e-9 (NOT -inf), applied
// after the SCALE multiply, before softmax.
//
// Smem: Qs[64][64] (plain, d-contiguous; a-operand reads are ty-broadcast
//         LDS.128),
//       KPs[64][64] XOR-swizzled (phys = c*64 + (x ^ 4*((c>>2)&15))); holds
//         the K tile during QK^T and is reused for the transposed P tile.
//         Swizzle term is 4-aligned, so 4-aligned d-runs stay contiguous ->
//         K b-operand reads are LDS.128 too,
//       Vs[64][64] plain ([c][d], d-contiguous; b-operand reads LDS.128).
// Total = exactly 48 KB static -> 4 CTAs/SM, 32 warps.
// ---------------------------------------------------------------------------
__device__ __forceinline__ int kp_sw(int c, int x) {
  return (c << 6) + (x ^ ((((unsigned)c >> 2) & 15) << 2));
}

__global__ __launch_bounds__(256) void attn_kernel(const int* __restrict__ mask) {
  __shared__ float Qs[64 * 64];
  __shared__ float KPs[64 * 64];
  __shared__ float Vs[64 * 64];

  const int t = threadIdx.x;
  const int tx = t & 15, ty = t >> 4;
  const int q0 = blockIdx.x << 6;
  const int h = blockIdx.y;
  const int b = blockIdx.z;
  const int hoff = h * DH;

  const float* qbase = g_q + (b * SEQ + q0) * DIMC + hoff;
  const float* kbase = g_k + (b * SEQ) * DIMC + hoff;
  const float* vbase = g_v + (b * SEQ) * DIMC + hoff;
  const int* mbase = mask + b * SEQ;

  // Load Q tile [64 rows][64 dims], plain layout (stride 64).
#pragma unroll
  for (int i = 0; i < 4; i++) {
    int lin = t + i * 256;
    int r = lin >> 4;
    int d4 = (lin & 15) << 2;
    *(float4*)&Qs[(r << 6) + d4] = *(const float4*)(qbase + r * DIMC + d4);
  }

  float m[4], l[4], acc[4][4];
#pragma unroll
  for (int i = 0; i < 4; i++) {
    m[i] = -1e30f;
    l[i] = 0.f;
#pragma unroll
    for (int j = 0; j < 4; j++) acc[i][j] = 0.f;
  }

  for (int kt = 0; kt < SEQ / 64; kt++) {
    const int c0 = kt << 6;
    __syncthreads();  // prior GEMM2 finished with KPs(P) and Vs

    // Load K tile (swizzled) and V tile (plain), 4 float4 each per thread.
#pragma unroll
    for (int i = 0; i < 4; i++) {
      int lin = t + i * 256;
      int c = lin >> 4;
      int d4 = (lin & 15) << 2;
      float4 kv = *(const float4*)(kbase + (c0 + c) * DIMC + d4);
      float4 vv = *(const float4*)(vbase + (c0 + c) * DIMC + d4);
      *(float4*)&KPs[kp_sw(c, d4)] = kv;
      *(float4*)&Vs[(c << 6) + d4] = vv;
    }
    // Per-key-column mask bits for this thread's 4 columns (L2-hot LDG).
    int mk[4];
#pragma unroll
    for (int j = 0; j < 4; j++) mk[j] = mbase[c0 + (tx << 2) + j];
    __syncthreads();

    // GEMM1: S[r][c] = sum_d Q[r][d] * K[c][d].
    // d unrolled by 4; both operands LDS.128 (swizzle preserves 4-runs):
    // 8 LDS.128 : 64 FFMA per d-group.
    float s[4][4];
#pragma unroll
    for (int i = 0; i < 4; i++)
#pragma unroll
      for (int j = 0; j < 4; j++) s[i][j] = 0.f;

    const int fsw = tx << 2;  // kp swizzle term for c = 4*tx + j (j<4)
#pragma unroll
    for (int d0 = 0; d0 < 64; d0 += 4) {
      float4 aq[4], bk[4];
#pragma unroll
      for (int i = 0; i < 4; i++)
        aq[i] = *(const float4*)&Qs[(((ty << 2) + i) << 6) + d0];
#pragma unroll
      for (int j = 0; j < 4; j++)
        bk[j] = *(const float4*)&KPs[(((tx << 2) + j) << 6) + (d0 ^ fsw)];
#pragma unroll
      for (int i = 0; i < 4; i++) {
        float a0 = aq[i].x, a1 = aq[i].y, a2 = aq[i].z, a3 = aq[i].w;
#pragma unroll
        for (int j = 0; j < 4; j++) {
          float r = s[i][j];
          r = fmaf(a0, bk[j].x, r);
          r = fmaf(a1, bk[j].y, r);
          r = fmaf(a2, bk[j].z, r);
          r = fmaf(a3, bk[j].w, r);
          s[i][j] = r;
        }
      }
    }

    // Scale + constant-fill mask + online softmax (row groups = 16 tx lanes).
#pragma unroll
    for (int i = 0; i < 4; i++) {
      float sv[4];
#pragma unroll
      for (int j = 0; j < 4; j++) {
        float xsc = s[i][j] * ATT_SCALE;
        sv[j] = (mk[j] != 0) ? xsc : 1e-9f;
      }
      float tm = fmaxf(fmaxf(sv[0], sv[1]), fmaxf(sv[2], sv[3]));
#pragma unroll
      for (int off = 8; off > 0; off >>= 1)
        tm = fmaxf(tm, __shfl_xor_sync(0xffffffffu, tm, off, 16));
      float mn = fmaxf(m[i], tm);
      float alpha = __expf(m[i] - mn);
      float rs = 0.f;
#pragma unroll
      for (int j = 0; j < 4; j++) {
        sv[j] = __expf(sv[j] - mn);
        rs += sv[j];
      }
#pragma unroll
      for (int off = 8; off > 0; off >>= 1)
        rs += __shfl_xor_sync(0xffffffffu, rs, off, 16);
      l[i] = l[i] * alpha + rs;
      m[i] = mn;
#pragma unroll
      for (int j = 0; j < 4; j++) {
        acc[i][j] *= alpha;
        s[i][j] = sv[j];
      }
    }

    __syncthreads();  // all threads done reading K tile
    // Store P transposed into KPs: P[c][r], same swizzle.
#pragma unroll
    for (int j = 0; j < 4; j++) {
      int c = (tx << 2) + j;
#pragma unroll
      for (int i = 0; i < 4; i++)
        KPs[(c << 6) + (((ty << 2) + i) ^ fsw)] = s[i][j];
    }
    __syncthreads();

    // GEMM2: O[r][dim] += sum_c P[c][r] * V[c][dim]  (both operands LDS.128)
#pragma unroll
    for (int c = 0; c < 64; c++) {
      int f = ((((unsigned)c >> 2) & 15) << 2);
      float4 a4 = *(const float4*)&KPs[(c << 6) + ((ty << 2) ^ f)];
      float4 b4 = *(const float4*)&Vs[(c << 6) + (tx << 2)];
      float ar[4] = {a4.x, a4.y, a4.z, a4.w};
      float br[4] = {b4.x, b4.y, b4.z, b4.w};
#pragma unroll
      for (int i = 0; i < 4; i++)
#pragma unroll
        for (int j = 0; j < 4; j++) acc[i][j] = fmaf(ar[i], br[j], acc[i][j]);
    }
  }

  // Normalize and write head-major channel layout: channel = h*64 + dim.
  float* obase = g_att + (b * SEQ + q0) * DIMC + hoff;
#pragma unroll
  for (int i = 0; i < 4; i++) {
    float inv = 1.f / l[i];
    float4 v = make_float4(acc[i][0] * inv, acc[i][1] * inv,
                           acc[i][2] * inv, acc[i][3] * inv);
    *(float4*)&obase[((ty << 2) + i) * DIMC + (tx << 2)] = v;
  }
}

// ---------------------------------------------------------------------------
extern "C" void kernel_launch(void* const* d_in, const int* in_sizes, int n_in,
                              void* d_out, int out_size) {
  const float* x    = (const float*)d_in[0];
  const int*   mask = (const int*)d_in[1];
  const float* Wq   = (const float*)d_in[2];
  const float* Wk   = (const float*)d_in[3];
  const float* Wv   = (const float*)d_in[4];
  const float* Wout = (const float*)d_in[5];
  float* out = (float*)d_out;
  (void)in_sizes; (void)n_in; (void)out_size;

  dim3 gq(DIMC / 64, TOK / 64, 3);      // 8 x 128 x 3
  qkv_gemm<<<gq, 256>>>(x, Wq, Wk, Wv);

  dim3 ga(SEQ / 64, HEADS, BATCH);      // 32 x 8 x 4
  attn_kernel<<<ga, 256>>>(mask);

  dim3 go(DIMC / 64, TOK / 64);         // 8 x 128
  out_gemm<<<go, 256>>>(Wout, out);
}

// round 7
// speedup vs baseline: 1.1044x; 1.1044x over previous
#include <cuda_runtime.h>

// CrossModalAttention: B=4, N=2048, DIM=512, H=8, Dh=64, fp32.
// Pipeline: [qkv_gemm] -> [attn_kernel (flash, constant-fill mask)] -> [out_gemm]
// Round 7 (= Round 4/5/6 resubmit; broker timed out before it ever ran):
// packed fp32 math via PTX fma.rn.f32x2 (FFMA2) — 2 FMAs per fma-pipe
// issue slot. ptxas never emits these from plain C++.

#define HEADS 8
#define DH 64
#define DIMC 512
#define BATCH 4
#define SEQ 2048
#define TOK (BATCH * SEQ)           // 8192
#define ATT_SCALE 0.125f            // 64^-0.5

typedef unsigned long long u64;

__device__ __forceinline__ u64 pack2(float lo, float hi) {
  u64 r; asm("mov.b64 %0, {%1, %2};" : "=l"(r) : "f"(lo), "f"(hi)); return r;
}
__device__ __forceinline__ void unpack2(u64 v, float& lo, float& hi) {
  asm("mov.b64 {%0, %1}, %2;" : "=f"(lo), "=f"(hi) : "l"(v));
}
__device__ __forceinline__ u64 fma2(u64 a, u64 b, u64 c) {
  u64 d; asm("fma.rn.f32x2 %0, %1, %2, %3;" : "=l"(d) : "l"(a), "l"(b), "l"(c));
  return d;
}
__device__ __forceinline__ u64 mul2(u64 a, u64 b) {
  u64 d; asm("mul.rn.f32x2 %0, %1, %2;" : "=l"(d) : "l"(a), "l"(b));
  return d;
}

// Scratch (allocation-free rule: __device__ globals). 4 x 16 MB.
__device__ float g_q[TOK * DIMC];
__device__ float g_k[TOK * DIMC];
__device__ float g_v[TOK * DIMC];
__device__ float g_att[TOK * DIMC];

// ---------------------------------------------------------------------------
// GEMM: C[m][n] = sum_k A[m*K+k] * B[n*K+k]. 64x64 tile, BK=16, 256 thr,
// 4x4 micro-tile. Inner step: 2 LDS.128 + 4 pack-MOV (non-fma pipe) + 8 FFMA2.
// Accumulators packed over the j (output) dim; b-pairs come straight from
// the float4, only the broadcast a needs packing.
// ---------------------------------------------------------------------------
__device__ __forceinline__ void gemm_body(const float* __restrict__ A,
                                          const float* __restrict__ B,
                                          float* __restrict__ C) {
  __shared__ __align__(16) float As[16][68];
  __shared__ __align__(16) float Bs[16][68];
  const int t = threadIdx.x;
  const int tx = t & 15, ty = t >> 4;
  const int row0 = blockIdx.y << 6;
  const int col0 = blockIdx.x << 6;
  const int lr = t >> 2;            // 0..63 tile row
  const int lk = (t & 3) << 2;      // 0,4,8,12 k-offset
  const float* Ag = A + (row0 + lr) * DIMC + lk;
  const float* Bg = B + (col0 + lr) * DIMC + lk;

  u64 acc2[4][2];
#pragma unroll
  for (int i = 0; i < 4; i++) {
    acc2[i][0] = pack2(0.f, 0.f);
    acc2[i][1] = pack2(0.f, 0.f);
  }

  float4 av = *(const float4*)(Ag);
  float4 bv = *(const float4*)(Bg);

  for (int k0 = 0; k0 < DIMC; k0 += 16) {
    As[lk + 0][lr] = av.x; As[lk + 1][lr] = av.y;
    As[lk + 2][lr] = av.z; As[lk + 3][lr] = av.w;
    Bs[lk + 0][lr] = bv.x; Bs[lk + 1][lr] = bv.y;
    Bs[lk + 2][lr] = bv.z; Bs[lk + 3][lr] = bv.w;
    __syncthreads();
    if (k0 + 16 < DIMC) {          // prefetch next k-tile during compute
      av = *(const float4*)(Ag + k0 + 16);
      bv = *(const float4*)(Bg + k0 + 16);
    }
#pragma unroll
    for (int k = 0; k < 16; k++) {
      float4 a4 = *(const float4*)&As[k][ty << 2];
      ulonglong2 b2 = *(const ulonglong2*)&Bs[k][tx << 2];
      float ar[4] = {a4.x, a4.y, a4.z, a4.w};
#pragma unroll
      for (int i = 0; i < 4; i++) {
        u64 ai = pack2(ar[i], ar[i]);
        acc2[i][0] = fma2(ai, b2.x, acc2[i][0]);
        acc2[i][1] = fma2(ai, b2.y, acc2[i][1]);
      }
    }
    __syncthreads();
  }
#pragma unroll
  for (int i = 0; i < 4; i++) {
    float4 v;
    unpack2(acc2[i][0], v.x, v.y);
    unpack2(acc2[i][1], v.z, v.w);
    *(float4*)&C[(row0 + (ty << 2) + i) * DIMC + col0 + (tx << 2)] = v;
  }
}

__global__ __launch_bounds__(256) void qkv_gemm(const float* __restrict__ x,
                                                const float* __restrict__ Wq,
                                                const float* __restrict__ Wk,
                                                const float* __restrict__ Wv) {
  const float* W = (blockIdx.z == 0) ? Wq : (blockIdx.z == 1) ? Wk : Wv;
  float* C = (blockIdx.z == 0) ? g_q : (blockIdx.z == 1) ? g_k : g_v;
  gemm_body(x, W, C);
}

__global__ __launch_bounds__(256) void out_gemm(const float* __restrict__ Wout,
                                                float* __restrict__ out) {
  gemm_body(g_att, Wout, out);
}

// ---------------------------------------------------------------------------
// Flash attention, fp32, one block per (q-tile of 64 rows, head, batch).
// Reference-faithful masking: masked score = constant 1e-9 (NOT -inf), applied
// after the SCALE multiply, before softmax.
//
// GEMM1 packs over the reduction dim d: Q and K pairs are adjacent in smem
// (swizzle term is 4-aligned, so ulonglong2 loads stay legal) -> zero pack
// MOVs; one horizontal add per score at the end.
// GEMM2 packs over the output dim j (V pairs adjacent; broadcast P packed).
// Smem 48 KB static.
// ---------------------------------------------------------------------------
__device__ __forceinline__ int kp_sw(int c, int x) {
  return (c << 6) + (x ^ ((((unsigned)c >> 2) & 15) << 2));
}

__global__ __launch_bounds__(256) void attn_kernel(const int* __restrict__ mask) {
  __shared__ __align__(16) float Qs[64 * 64];
  __shared__ __align__(16) float KPs[64 * 64];
  __shared__ __align__(16) float Vs[64 * 64];

  const int t = threadIdx.x;
  const int tx = t & 15, ty = t >> 4;
  const int q0 = blockIdx.x << 6;
  const int h = blockIdx.y;
  const int b = blockIdx.z;
  const int hoff = h * DH;

  const float* qbase = g_q + (b * SEQ + q0) * DIMC + hoff;
  const float* kbase = g_k + (b * SEQ) * DIMC + hoff;
  const float* vbase = g_v + (b * SEQ) * DIMC + hoff;
  const int* mbase = mask + b * SEQ;

  // Load Q tile [64 rows][64 dims], plain layout (stride 64).
#pragma unroll
  for (int i = 0; i < 4; i++) {
    int lin = t + i * 256;
    int r = lin >> 4;
    int d4 = (lin & 15) << 2;
    *(float4*)&Qs[(r << 6) + d4] = *(const float4*)(qbase + r * DIMC + d4);
  }

  float m[4], l[4];
  u64 acc2[4][2];
#pragma unroll
  for (int i = 0; i < 4; i++) {
    m[i] = -1e30f;
    l[i] = 0.f;
    acc2[i][0] = pack2(0.f, 0.f);
    acc2[i][1] = pack2(0.f, 0.f);
  }

  for (int kt = 0; kt < SEQ / 64; kt++) {
    const int c0 = kt << 6;
    __syncthreads();  // prior GEMM2 finished with KPs(P) and Vs

    // Load K tile (swizzled) and V tile (plain), 4 float4 each per thread.
#pragma unroll
    for (int i = 0; i < 4; i++) {
      int lin = t + i * 256;
      int c = lin >> 4;
      int d4 = (lin & 15) << 2;
      float4 kv = *(const float4*)(kbase + (c0 + c) * DIMC + d4);
      float4 vv = *(const float4*)(vbase + (c0 + c) * DIMC + d4);
      *(float4*)&KPs[kp_sw(c, d4)] = kv;
      *(float4*)&Vs[(c << 6) + d4] = vv;
    }
    // Per-key-column mask bits for this thread's 4 columns (L2-hot LDG).
    int mk[4];
#pragma unroll
    for (int j = 0; j < 4; j++) mk[j] = mbase[c0 + (tx << 2) + j];
    __syncthreads();

    // GEMM1: S[r][c] = sum_d Q[r][d] * K[c][d], packed over d-parity.
    // Per d-group: 8 LDS.128 + 32 FFMA2 (=64 FMAs), zero pack MOVs.
    u64 s2[4][4];
#pragma unroll
    for (int i = 0; i < 4; i++)
#pragma unroll
      for (int j = 0; j < 4; j++) s2[i][j] = pack2(0.f, 0.f);

    const int fsw = tx << 2;  // kp swizzle term for c = 4*tx + j (j<4)
#pragma unroll
    for (int d0 = 0; d0 < 64; d0 += 4) {
      ulonglong2 aq[4], bk[4];
#pragma unroll
      for (int i = 0; i < 4; i++)
        aq[i] = *(const ulonglong2*)&Qs[(((ty << 2) + i) << 6) + d0];
#pragma unroll
      for (int j = 0; j < 4; j++)
        bk[j] = *(const ulonglong2*)&KPs[(((tx << 2) + j) << 6) + (d0 ^ fsw)];
#pragma unroll
      for (int i = 0; i < 4; i++)
#pragma unroll
        for (int j = 0; j < 4; j++) {
          s2[i][j] = fma2(aq[i].x, bk[j].x, s2[i][j]);
          s2[i][j] = fma2(aq[i].y, bk[j].y, s2[i][j]);
        }
    }

    // Scale + constant-fill mask + online softmax (row groups = 16 tx lanes).
    float s[4][4];
#pragma unroll
    for (int i = 0; i < 4; i++)
#pragma unroll
      for (int j = 0; j < 4; j++) {
        float lo, hi;
        unpack2(s2[i][j], lo, hi);
        s[i][j] = lo + hi;
      }

#pragma unroll
    for (int i = 0; i < 4; i++) {
      float sv[4];
#pragma unroll
      for (int j = 0; j < 4; j++) {
        float xsc = s[i][j] * ATT_SCALE;
        sv[j] = (mk[j] != 0) ? xsc : 1e-9f;
      }
      float tm = fmaxf(fmaxf(sv[0], sv[1]), fmaxf(sv[2], sv[3]));
#pragma unroll
      for (int off = 8; off > 0; off >>= 1)
        tm = fmaxf(tm, __shfl_xor_sync(0xffffffffu, tm, off, 16));
      float mn = fmaxf(m[i], tm);
      float alpha = __expf(m[i] - mn);
      float rs = 0.f;
#pragma unroll
      for (int j = 0; j < 4; j++) {
        sv[j] = __expf(sv[j] - mn);
        rs += sv[j];
      }
#pragma unroll
      for (int off = 8; off > 0; off >>= 1)
        rs += __shfl_xor_sync(0xffffffffu, rs, off, 16);
      l[i] = l[i] * alpha + rs;
      m[i] = mn;
      u64 al2 = pack2(alpha, alpha);
      acc2[i][0] = mul2(acc2[i][0], al2);
      acc2[i][1] = mul2(acc2[i][1], al2);
#pragma unroll
      for (int j = 0; j < 4; j++) s[i][j] = sv[j];
    }

    __syncthreads();  // all threads done reading K tile
    // Store P transposed into KPs: P[c][r], same swizzle.
#pragma unroll
    for (int j = 0; j < 4; j++) {
      int c = (tx << 2) + j;
#pragma unroll
      for (int i = 0; i < 4; i++)
        KPs[(c << 6) + (((ty << 2) + i) ^ fsw)] = s[i][j];
    }
    __syncthreads();

    // GEMM2: O[r][dim] += sum_c P[c][r] * V[c][dim], packed over j.
    // Per c: 2 LDS.128 + 4 pack-MOV + 8 FFMA2.
#pragma unroll
    for (int c = 0; c < 64; c++) {
      int f = ((((unsigned)c >> 2) & 15) << 2);
      float4 a4 = *(const float4*)&KPs[(c << 6) + ((ty << 2) ^ f)];
      ulonglong2 b2 = *(const ulonglong2*)&Vs[(c << 6) + (tx << 2)];
      float ar[4] = {a4.x, a4.y, a4.z, a4.w};
#pragma unroll
      for (int i = 0; i < 4; i++) {
        u64 ai = pack2(ar[i], ar[i]);
        acc2[i][0] = fma2(ai, b2.x, acc2[i][0]);
        acc2[i][1] = fma2(ai, b2.y, acc2[i][1]);
      }
    }
  }

  // Normalize and write head-major channel layout: channel = h*64 + dim.
  float* obase = g_att + (b * SEQ + q0) * DIMC + hoff;
#pragma unroll
  for (int i = 0; i < 4; i++) {
    float inv = 1.f / l[i];
    u64 inv2 = pack2(inv, inv);
    u64 o0 = mul2(acc2[i][0], inv2);
    u64 o1 = mul2(acc2[i][1], inv2);
    float4 v;
    unpack2(o0, v.x, v.y);
    unpack2(o1, v.z, v.w);
    *(float4*)&obase[((ty << 2) + i) * DIMC + (tx << 2)] = v;
  }
}

// ---------------------------------------------------------------------------
extern "C" void kernel_launch(void* const* d_in, const int* in_sizes, int n_in,
                              void* d_out, int out_size) {
  const float* x    = (const float*)d_in[0];
  const int*   mask = (const int*)d_in[1];
  const float* Wq   = (const float*)d_in[2];
  const float* Wk   = (const float*)d_in[3];
  const float* Wv   = (const float*)d_in[4];
  const float* Wout = (const float*)d_in[5];
  float* out = (float*)d_out;
  (void)in_sizes; (void)n_in; (void)out_size;

  dim3 gq(DIMC / 64, TOK / 64, 3);      // 8 x 128 x 3
  qkv_gemm<<<gq, 256>>>(x, Wq, Wk, Wv);

  dim3 ga(SEQ / 64, HEADS, BATCH);      // 32 x 8 x 4
  attn_kernel<<<ga, 256>>>(mask);

  dim3 go(DIMC / 64, TOK / 64);         // 8 x 128
  out_gemm<<<go, 256>>>(Wout, out);
}